// round 3
// baseline (speedup 1.0000x reference)
#include <cuda_runtime.h>
#include <cstdint>

#define NN 100000
#define FF 64

// ---------------- scratch (device globals: no runtime allocation) ----------
__device__ float g_sum_pos[(size_t)NN * FF];
__device__ float g_sum_neg[(size_t)NN * FF];
__device__ float g_cnt_pos[NN];
__device__ float g_cnt_neg[NN];
__device__ float g_hb[136]; // [0:64) hb_pos, [64:128) hb_neg, [128] y2_pos, [129] y2_neg

__device__ __forceinline__ float wsum(float v) {
#pragma unroll
    for (int o = 16; o > 0; o >>= 1) v += __shfl_xor_sync(0xffffffffu, v, o);
    return v;
}

// ---------------- hyperbolic bias precompute: proj(expmap0(b, c=1)) --------
__global__ void bias_kernel(const float* __restrict__ bp, const float* __restrict__ bn) {
    int lane = threadIdx.x;
    if (lane >= 32) return;
    const float* bs[2] = {bp, bn};
#pragma unroll
    for (int i = 0; i < 2; ++i) {
        float u0 = bs[i][lane], u1 = bs[i][lane + 32];
        float n = fmaxf(sqrtf(wsum(u0 * u0 + u1 * u1)), 1e-15f);
        float s = tanhf(n) / n;
        float v0 = u0 * s, v1 = u1 * s;
        float vn = fmaxf(sqrtf(wsum(v0 * v0 + v1 * v1)), 1e-15f);
        if (vn > 0.996f) { float p = 0.996f / vn; v0 *= p; v1 *= p; }
        g_hb[i * 64 + lane]      = v0;
        g_hb[i * 64 + 32 + lane] = v1;
        float y2 = wsum(v0 * v0 + v1 * v1);
        if (lane == 0) g_hb[128 + i] = y2;
    }
}

// ---------------- scatter-sum + count over edges ---------------------------
// One thread per (edge, 16B chunk): 16 threads per edge, vectorized red.
__global__ void scatter_kernel(const float* __restrict__ x, const int* __restrict__ ei,
                               float* __restrict__ sum, float* __restrict__ cnt, int E) {
    long tid = (long)blockIdx.x * blockDim.x + threadIdx.x;
    long e = tid >> 4;
    int ch = (int)(tid & 15);
    if (e >= E) return;
    int src = ei[e];
    int dst = ei[(long)E + e];
    float4 v = *reinterpret_cast<const float4*>(x + (size_t)src * FF + ch * 4);
    float* a = sum + (size_t)dst * FF + ch * 4;
    asm volatile("red.global.add.v4.f32 [%0], {%1,%2,%3,%4};"
                 :: "l"(a), "f"(v.x), "f"(v.y), "f"(v.z), "f"(v.w) : "memory");
    if (ch == 0) atomicAdd(cnt + dst, 1.0f);
}

// ---------------- mobius_matvec + proj (c = 1) -----------------------------
__device__ __forceinline__ void matvec_proj(float m0, float m1, float xn,
                                            float& r0, float& r1) {
    float msq = wsum(m0 * m0 + m1 * m1);
    float mn = fmaxf(sqrtf(msq), 1e-15f);
    float art = atanhf(fminf(xn, 1.0f - 1e-7f));
    float sc = tanhf(mn / xn * art) / mn;
    r0 = m0 * sc; r1 = m1 * sc;
    float rsq = wsum(r0 * r0 + r1 * r1);
    float rn = fmaxf(sqrtf(rsq), 1e-15f);
    if (rn > 0.996f) { float s = 0.996f / rn; r0 *= s; r1 *= s; }
}

// out = proj(matvec(agg)) + proj(mobius_add(proj(matvec(x)), hyp_bias))
__device__ __forceinline__ void node_out(
    float aP0, float aP1, float pn,       // matvec acc from agg branch + agg norm
    float aC0, float aC1, float xn,       // matvec acc from x branch + x norm
    float hb0, float hb1, float y2,
    float& o0, float& o1) {
    float r0, r1; matvec_proj(aP0, aP1, pn, r0, r1);
    float s0, s1; matvec_proj(aC0, aC1, xn, s0, s1);
    float x2 = wsum(s0 * s0 + s1 * s1);
    float xy = wsum(s0 * hb0 + s1 * hb1);
    float f1 = 1.0f + 2.0f * xy + y2;
    float f2 = 1.0f - x2;
    float den = fmaxf(1.0f + 2.0f * xy + x2 * y2, 1e-15f);
    float q0 = (f1 * s0 + f2 * hb0) / den;
    float q1 = (f1 * s1 + f2 * hb1) / den;
    float qn = fmaxf(sqrtf(wsum(q0 * q0 + q1 * q1)), 1e-15f);
    if (qn > 0.996f) { float p = 0.996f / qn; q0 *= p; q1 *= p; }
    o0 = r0 + q0; o1 = r1 + q1;
}

// ---------------- main per-node kernel: warp handles 2 nodes ---------------
__global__ void compute_kernel(const float* __restrict__ x,
                               const float* __restrict__ Wp,  const float* __restrict__ Wpc,
                               const float* __restrict__ Wn,  const float* __restrict__ Wnc,
                               float* __restrict__ out, int n) {
    extern __shared__ float sh[];
    float* sWp  = sh;
    float* sWpc = sh + 64 * 65;
    float* sWn  = sh + 2 * 64 * 65;
    float* sWnc = sh + 3 * 64 * 65;
    // transpose into shared: s[k*65 + o] = W[o*64 + k]; pitch 65 -> conflict-free
    for (int idx = threadIdx.x; idx < 4096; idx += blockDim.x) {
        int o = idx >> 6, k = idx & 63;
        int d = k * 65 + o;
        sWp[d]  = Wp[idx];
        sWpc[d] = Wpc[idx];
        sWn[d]  = Wn[idx];
        sWnc[d] = Wnc[idx];
    }
    __syncthreads();

    const unsigned FULL = 0xffffffffu;
    int lane = threadIdx.x & 31;
    int gw = (int)((blockIdx.x * blockDim.x + threadIdx.x) >> 5);
    int nw = (int)((gridDim.x * blockDim.x) >> 5);

    float hbp0 = g_hb[lane],      hbp1 = g_hb[32 + lane];
    float hbn0 = g_hb[64 + lane], hbn1 = g_hb[96 + lane];
    float y2p = g_hb[128], y2n = g_hb[129];

    for (long i = (long)gw * 2; i < n; i += (long)nw * 2) {
        bool twoB = (i + 1 < n);
        long iB = twoB ? i + 1 : i;

        float xA0 = x[i * 64 + lane],  xA1 = x[i * 64 + 32 + lane];
        float xB0 = x[iB * 64 + lane], xB1 = x[iB * 64 + 32 + lane];
        float rpA = 1.0f / fmaxf(g_cnt_pos[i], 1.0f);
        float rnA = 1.0f / fmaxf(g_cnt_neg[i], 1.0f);
        float rpB = 1.0f / fmaxf(g_cnt_pos[iB], 1.0f);
        float rnB = 1.0f / fmaxf(g_cnt_neg[iB], 1.0f);
        float pA0 = g_sum_pos[i * 64 + lane] * rpA,  pA1 = g_sum_pos[i * 64 + 32 + lane] * rpA;
        float nA0 = g_sum_neg[i * 64 + lane] * rnA,  nA1 = g_sum_neg[i * 64 + 32 + lane] * rnA;
        float pB0 = g_sum_pos[iB * 64 + lane] * rpB, pB1 = g_sum_pos[iB * 64 + 32 + lane] * rpB;
        float nB0 = g_sum_neg[iB * 64 + lane] * rnB, nB1 = g_sum_neg[iB * 64 + 32 + lane] * rnB;

        // input norms (clipped)
        float xnA = fmaxf(sqrtf(wsum(xA0 * xA0 + xA1 * xA1)), 1e-15f);
        float pnA = fmaxf(sqrtf(wsum(pA0 * pA0 + pA1 * pA1)), 1e-15f);
        float nnA = fmaxf(sqrtf(wsum(nA0 * nA0 + nA1 * nA1)), 1e-15f);
        float xnB = fmaxf(sqrtf(wsum(xB0 * xB0 + xB1 * xB1)), 1e-15f);
        float pnB = fmaxf(sqrtf(wsum(pB0 * pB0 + pB1 * pB1)), 1e-15f);
        float nnB = fmaxf(sqrtf(wsum(nB0 * nB0 + nB1 * nB1)), 1e-15f);

        float aPp0 = 0, aPp1 = 0, aPc0 = 0, aPc1 = 0, aNp0 = 0, aNp1 = 0, aNc0 = 0, aNc1 = 0;
        float bPp0 = 0, bPp1 = 0, bPc0 = 0, bPc1 = 0, bNp0 = 0, bNp1 = 0, bNc0 = 0, bNc1 = 0;

#pragma unroll
        for (int half = 0; half < 2; ++half) {
            float vxA = half ? xA1 : xA0, vpA = half ? pA1 : pA0, vnA = half ? nA1 : nA0;
            float vxB = half ? xB1 : xB0, vpB = half ? pB1 : pB0, vnB = half ? nB1 : nB0;
#pragma unroll
            for (int kk = 0; kk < 32; ++kk) {
                int k = half * 32 + kk;
                float xa = __shfl_sync(FULL, vxA, kk);
                float pa = __shfl_sync(FULL, vpA, kk);
                float na = __shfl_sync(FULL, vnA, kk);
                float xb = __shfl_sync(FULL, vxB, kk);
                float pb = __shfl_sync(FULL, vpB, kk);
                float nb = __shfl_sync(FULL, vnB, kk);
                int d = k * 65 + lane;
                float wp0 = sWp[d],  wp1 = sWp[d + 32];
                float wc0 = sWpc[d], wc1 = sWpc[d + 32];
                float wn0 = sWn[d],  wn1 = sWn[d + 32];
                float wq0 = sWnc[d], wq1 = sWnc[d + 32];
                aPp0 = fmaf(pa, wp0, aPp0); aPp1 = fmaf(pa, wp1, aPp1);
                aPc0 = fmaf(xa, wc0, aPc0); aPc1 = fmaf(xa, wc1, aPc1);
                aNp0 = fmaf(na, wn0, aNp0); aNp1 = fmaf(na, wn1, aNp1);
                aNc0 = fmaf(xa, wq0, aNc0); aNc1 = fmaf(xa, wq1, aNc1);
                bPp0 = fmaf(pb, wp0, bPp0); bPp1 = fmaf(pb, wp1, bPp1);
                bPc0 = fmaf(xb, wc0, bPc0); bPc1 = fmaf(xb, wc1, bPc1);
                bNp0 = fmaf(nb, wn0, bNp0); bNp1 = fmaf(nb, wn1, bNp1);
                bNc0 = fmaf(xb, wq0, bNc0); bNc1 = fmaf(xb, wq1, bNc1);
            }
        }

        float oP0, oP1, oN0, oN1;
        node_out(aPp0, aPp1, pnA, aPc0, aPc1, xnA, hbp0, hbp1, y2p, oP0, oP1);
        node_out(aNp0, aNp1, nnA, aNc0, aNc1, xnA, hbn0, hbn1, y2n, oN0, oN1);
        out[i * 128 + lane]      = oP0;
        out[i * 128 + 32 + lane] = oP1;
        out[i * 128 + 64 + lane] = oN0;
        out[i * 128 + 96 + lane] = oN1;

        if (twoB) {
            node_out(bPp0, bPp1, pnB, bPc0, bPc1, xnB, hbp0, hbp1, y2p, oP0, oP1);
            node_out(bNp0, bNp1, nnB, bNc0, bNc1, xnB, hbn0, hbn1, y2n, oN0, oN1);
            out[iB * 128 + lane]      = oP0;
            out[iB * 128 + 32 + lane] = oP1;
            out[iB * 128 + 64 + lane] = oN0;
            out[iB * 128 + 96 + lane] = oN1;
        }
    }
}

// ---------------------------------------------------------------------------
extern "C" void kernel_launch(void* const* d_in, const int* in_sizes, int n_in,
                              void* d_out, int out_size) {
    const float* x   = (const float*)d_in[0];
    const float* Wp  = (const float*)d_in[1];
    const float* Wpc = (const float*)d_in[2];
    const float* bpc = (const float*)d_in[3];
    const float* Wn  = (const float*)d_in[4];
    const float* Wnc = (const float*)d_in[5];
    const float* bnc = (const float*)d_in[6];
    const int* pei   = (const int*)d_in[7];
    const int* nei   = (const int*)d_in[8];
    float* out = (float*)d_out;

    int n = in_sizes[0] / 64;
    int E = in_sizes[7] / 2;

    void *psum_p, *psum_n, *pcnt_p, *pcnt_n;
    cudaGetSymbolAddress(&psum_p, g_sum_pos);
    cudaGetSymbolAddress(&psum_n, g_sum_neg);
    cudaGetSymbolAddress(&pcnt_p, g_cnt_pos);
    cudaGetSymbolAddress(&pcnt_n, g_cnt_neg);
    cudaMemsetAsync(psum_p, 0, (size_t)n * 64 * sizeof(float));
    cudaMemsetAsync(psum_n, 0, (size_t)n * 64 * sizeof(float));
    cudaMemsetAsync(pcnt_p, 0, (size_t)n * sizeof(float));
    cudaMemsetAsync(pcnt_n, 0, (size_t)n * sizeof(float));

    bias_kernel<<<1, 32>>>(bpc, bnc);

    long work = (long)E * 16;
    int thr = 256;
    int blocks = (int)((work + thr - 1) / thr);
    scatter_kernel<<<blocks, thr>>>(x, pei, (float*)psum_p, (float*)pcnt_p, E);
    scatter_kernel<<<blocks, thr>>>(x, nei, (float*)psum_n, (float*)pcnt_n, E);

    const int SMEM = 4 * 64 * 65 * (int)sizeof(float); // 66,560 B
    cudaFuncSetAttribute(compute_kernel, cudaFuncAttributeMaxDynamicSharedMemorySize, SMEM);
    compute_kernel<<<444, 256, SMEM>>>(x, Wp, Wpc, Wn, Wnc, out, n);
}